// round 4
// baseline (speedup 1.0000x reference)
#include <cuda_runtime.h>
#include <cuda_bf16.h>
#include <stdint.h>

// Problem constants
#define TT 6
#define BB 8
#define CC 192
#define HH 112
#define WW 112
#define KK 3
#define H0 56
#define W0 56
#define HWPIX (HH*WW)          // 12544
#define PIX (H0*W0)            // 3136
#define NN (TT*KK)             // 18 nodes
#define CG 8                   // channels per block in streaming kernels

// Scratch (static device globals — no allocation)
__device__ float g_feat[BB*NN*CC];          // node features [B][N=T*K][C]
__device__ float g_outk[BB*NN*CC];          // GCN output    [B][N][C]
__device__ float g_Wc[CC*CC];               // W_emb^T @ W_gcn

// ---------------------------------------------------------------------------
// Kernel 1: masked adaptive pooling (HBM-ceiling streaming).
__global__ __launch_bounds__(256) void pool_kernel(const float* __restrict__ x,
                                                   const int* __restrict__ masks) {
    int tb = blockIdx.x;          // t*B + b
    int cg = blockIdx.y;          // channel group
    int t = tb / BB, b = tb % BB;

    __shared__ float mf[3][PIX];
    __shared__ float red_s[8][24];

    const int* mp = masks + ((size_t)(b*TT + t) * KK) * PIX;
    for (int i = threadIdx.x; i < PIX; i += 256) {
        mf[0][i] = (float)(mp[i] & 1);
        mf[1][i] = (float)(mp[PIX + i] & 1);
        mf[2][i] = (float)(mp[2*PIX + i] & 1);
    }
    __syncthreads();

    const float* xbase = x + ((size_t)(t*BB + b)*CC + cg*CG) * HWPIX;

    float acc[CG][3];
    #pragma unroll
    for (int cc = 0; cc < CG; cc++) {
        acc[cc][0] = 0.f; acc[cc][1] = 0.f; acc[cc][2] = 0.f;
    }

    for (int i4 = threadIdx.x; i4 < HWPIX/4; i4 += 256) {
        int lin = i4 * 4;
        int h = lin / WW;
        int w = lin - h * WW;
        int mb = (h >> 1) * W0 + (w >> 1);
        float2 m0 = *(const float2*)&mf[0][mb];
        float2 m1 = *(const float2*)&mf[1][mb];
        float2 m2 = *(const float2*)&mf[2][mb];
        #pragma unroll
        for (int cc = 0; cc < CG; cc++) {
            float4 v = __ldcs((const float4*)(xbase + (size_t)cc*HWPIX + lin));
            float p0 = v.x + v.y, p1 = v.z + v.w;
            acc[cc][0] += p0 * m0.x + p1 * m0.y;
            acc[cc][1] += p0 * m1.x + p1 * m1.y;
            acc[cc][2] += p0 * m2.x + p1 * m2.y;
        }
    }

    int warp = threadIdx.x >> 5, lane = threadIdx.x & 31;
    #pragma unroll
    for (int cc = 0; cc < CG; cc++) {
        #pragma unroll
        for (int k = 0; k < 3; k++) {
            float s = acc[cc][k];
            #pragma unroll
            for (int off = 16; off; off >>= 1)
                s += __shfl_down_sync(0xFFFFFFFFu, s, off);
            if (lane == 0) red_s[warp][cc*3 + k] = s;
        }
    }
    __syncthreads();
    if (threadIdx.x < 24) {
        float s = 0.f;
        #pragma unroll
        for (int w8 = 0; w8 < 8; w8++) s += red_s[w8][threadIdx.x];
        int cc = threadIdx.x / 3, k = threadIdx.x % 3;
        int c = cg * CG + cc;
        g_feat[((size_t)(b*TT + t) * KK + k) * CC + c] = s * (1.0f / (float)HWPIX);
    }
}

// ---------------------------------------------------------------------------
// GCN kernel A: Wc[c][e] = sum_d W_emb[d][c] * W_gcn[d][e]
__global__ __launch_bounds__(192) void wc_kernel(const float* __restrict__ W_emb,
                                                 const float* __restrict__ W_gcn) {
    __shared__ float col[CC];
    int c = blockIdx.x, e = threadIdx.x;
    if (threadIdx.x < CC) col[threadIdx.x] = W_emb[(size_t)threadIdx.x * CC + c];
    __syncthreads();
    float acc = 0.f;
    #pragma unroll 8
    for (int d = 0; d < CC; d++)
        acc += col[d] * __ldg(&W_gcn[(size_t)d * CC + e]);
    g_Wc[c*CC + e] = acc;
}

// ---------------------------------------------------------------------------
// Fused GCN kernel: per-batch block does gram + softmax + sup + out, all smem.
// grid = BB (8 blocks) x 384 threads.
__global__ __launch_bounds__(384) void gcn_fused_kernel(const float* __restrict__ b_gcn) {
    __shared__ float node_s[NN*CC];     // 13.8 KB
    __shared__ float sup_s[NN*CC];      // 13.8 KB
    __shared__ float adj_s[NN*NN];      // 1.3 KB

    int b = blockIdx.x;
    int tid = threadIdx.x;              // 0..383

    const float* fb = g_feat + (size_t)b * NN * CC;
    for (int j = tid; j < NN*CC; j += 384)
        node_s[j] = fb[j];
    __syncthreads();

    // Gram: 324 dot products, one per thread (threads 324..383 idle)
    if (tid < NN*NN) {
        int n = tid / NN, m = tid % NN;
        float s = 0.f;
        #pragma unroll 4
        for (int c = 0; c < CC; c++)
            s += node_s[n*CC + c] * node_s[m*CC + c];
        adj_s[tid] = s;
    }
    __syncthreads();

    // Row softmax: one thread per row
    if (tid < NN) {
        float mx = -1e30f;
        #pragma unroll
        for (int m = 0; m < NN; m++) mx = fmaxf(mx, adj_s[tid*NN + m]);
        float sm = 0.f;
        #pragma unroll
        for (int m = 0; m < NN; m++) { float e = expf(adj_s[tid*NN + m] - mx); adj_s[tid*NN + m] = e; sm += e; }
        float inv = 1.0f / sm;
        #pragma unroll
        for (int m = 0; m < NN; m++) adj_s[tid*NN + m] *= inv;
    }

    // sup[n][d] = sum_c node[n][c] * Wc[c][d]   (runs concurrent with softmax;
    // uses only node_s + g_Wc, both ready). Split nodes in 2 halves.
    {
        int d = tid % CC;           // 0..191
        int half = tid / CC;        // 0 or 1
        float acc[9];
        #pragma unroll
        for (int q = 0; q < 9; q++) acc[q] = 0.f;
        for (int c = 0; c < CC; c++) {
            float w = __ldg(&g_Wc[c*CC + d]);
            #pragma unroll
            for (int q = 0; q < 9; q++)
                acc[q] += node_s[(half*9 + q)*CC + c] * w;
        }
        #pragma unroll
        for (int q = 0; q < 9; q++) sup_s[(half*9 + q)*CC + d] = acc[q];
    }
    __syncthreads();

    // out[n][d] = b_gcn[d] + sum_m adj[n][m] * sup[m][d]
    {
        int d = tid % CC;
        int half = tid / CC;
        float bg = __ldg(&b_gcn[d]);
        #pragma unroll
        for (int q = 0; q < 9; q++) {
            int n = half*9 + q;
            float o = bg;
            #pragma unroll
            for (int m = 0; m < NN; m++) o += adj_s[n*NN + m] * sup_s[m*CC + d];
            g_outk[((size_t)b*NN + n)*CC + d] = o;
        }
    }
}

// ---------------------------------------------------------------------------
// Kernel 3: residual scatter + add (HBM-ceiling streaming).
__global__ __launch_bounds__(256) void scatter_kernel(const float* __restrict__ x,
                                                      const int* __restrict__ masks,
                                                      float* __restrict__ out) {
    int tb = blockIdx.x;
    int cg = blockIdx.y;
    int t = tb / BB, b = tb % BB;

    __shared__ float mf[3][PIX];
    __shared__ float rs[CG][3];

    const int* mp = masks + ((size_t)(b*TT + t) * KK) * PIX;
    for (int i = threadIdx.x; i < PIX; i += 256) {
        mf[0][i] = (float)(mp[i] & 1);
        mf[1][i] = (float)(mp[PIX + i] & 1);
        mf[2][i] = (float)(mp[2*PIX + i] & 1);
    }
    if (threadIdx.x < CG*3) {
        int cc = threadIdx.x / 3, k = threadIdx.x % 3;
        rs[cc][k] = g_outk[((size_t)(b*TT + t) * KK + k) * CC + cg*CG + cc];
    }
    __syncthreads();

    float r[CG][3];
    #pragma unroll
    for (int cc = 0; cc < CG; cc++) {
        r[cc][0] = rs[cc][0]; r[cc][1] = rs[cc][1]; r[cc][2] = rs[cc][2];
    }

    size_t plane0 = ((size_t)(t*BB + b)*CC + cg*CG) * HWPIX;
    const float* xbase = x + plane0;
    float*       obase = out + plane0;

    for (int i4 = threadIdx.x; i4 < HWPIX/4; i4 += 256) {
        int lin = i4 * 4;
        int h = lin / WW;
        int w = lin - h * WW;
        int mb = (h >> 1) * W0 + (w >> 1);
        float2 m0 = *(const float2*)&mf[0][mb];
        float2 m1 = *(const float2*)&mf[1][mb];
        float2 m2 = *(const float2*)&mf[2][mb];
        #pragma unroll
        for (int cc = 0; cc < CG; cc++) {
            float4 v = __ldcs((const float4*)(xbase + (size_t)cc*HWPIX + lin));
            float c0 = r[cc][0]*m0.x + r[cc][1]*m1.x + r[cc][2]*m2.x;
            float c1 = r[cc][0]*m0.y + r[cc][1]*m1.y + r[cc][2]*m2.y;
            float4 o;
            o.x = v.x + c0; o.y = v.y + c0;
            o.z = v.z + c1; o.w = v.w + c1;
            __stcs((float4*)(obase + (size_t)cc*HWPIX + lin), o);
        }
    }
}

// ---------------------------------------------------------------------------
extern "C" void kernel_launch(void* const* d_in, const int* in_sizes, int n_in,
                              void* d_out, int out_size) {
    const float* x      = (const float*)d_in[0];
    const int*   masks  = (const int*)  d_in[1];
    const float* W_emb  = (const float*)d_in[2];
    const float* W_gcn  = (const float*)d_in[3];
    const float* b_gcn  = (const float*)d_in[4];
    float* out = (float*)d_out;

    dim3 grid(TT*BB, CC/CG);

    wc_kernel<<<CC, 192>>>(W_emb, W_gcn);
    pool_kernel<<<grid, 256>>>(x, masks);
    gcn_fused_kernel<<<BB, 384>>>(b_gcn);
    scatter_kernel<<<grid, 256>>>(x, masks, out);
}

// round 5
// speedup vs baseline: 1.0101x; 1.0101x over previous
#include <cuda_runtime.h>
#include <cuda_bf16.h>
#include <stdint.h>

// Problem constants
#define TT 6
#define BB 8
#define CC 192
#define HH 112
#define WW 112
#define KK 3
#define H0 56
#define W0 56
#define HWPIX (HH*WW)          // 12544
#define PIX (H0*W0)            // 3136
#define NN (TT*KK)             // 18 nodes
#define CG 8                   // channels per block in streaming kernels

// Scratch (static device globals — no allocation)
__device__ float g_feat[BB*NN*CC];          // node features [B][N=T*K][C]
__device__ float g_outk[BB*NN*CC];          // GCN output    [B][N][C]
__device__ float g_Wc[CC*CC];               // W_emb^T @ W_gcn

// ---------------------------------------------------------------------------
// Kernel 1: masked adaptive pooling (exact R2 structure — measured 82.6us,
// 71.8% DRAM; no cache hints, they regressed in R4).
__global__ __launch_bounds__(256) void pool_kernel(const float* __restrict__ x,
                                                   const int* __restrict__ masks) {
    int tb = blockIdx.x;          // t*B + b
    int cg = blockIdx.y;          // channel group
    int t = tb / BB, b = tb % BB;

    __shared__ float mf[3][PIX];
    __shared__ float red_s[8][24];

    const int* mp = masks + ((size_t)(b*TT + t) * KK) * PIX;
    for (int i = threadIdx.x; i < PIX; i += 256) {
        mf[0][i] = (float)(mp[i] & 1);
        mf[1][i] = (float)(mp[PIX + i] & 1);
        mf[2][i] = (float)(mp[2*PIX + i] & 1);
    }
    __syncthreads();

    const float* xbase = x + ((size_t)(t*BB + b)*CC + cg*CG) * HWPIX;

    float acc[CG][3];
    #pragma unroll
    for (int cc = 0; cc < CG; cc++) {
        acc[cc][0] = 0.f; acc[cc][1] = 0.f; acc[cc][2] = 0.f;
    }

    for (int i4 = threadIdx.x; i4 < HWPIX/4; i4 += 256) {
        int lin = i4 * 4;
        int h = lin / WW;
        int w = lin - h * WW;
        int mb = (h >> 1) * W0 + (w >> 1);
        float2 m0 = *(const float2*)&mf[0][mb];
        float2 m1 = *(const float2*)&mf[1][mb];
        float2 m2 = *(const float2*)&mf[2][mb];
        #pragma unroll
        for (int cc = 0; cc < CG; cc++) {
            float4 v = *(const float4*)(xbase + (size_t)cc*HWPIX + lin);
            float p0 = v.x + v.y, p1 = v.z + v.w;
            acc[cc][0] += p0 * m0.x + p1 * m0.y;
            acc[cc][1] += p0 * m1.x + p1 * m1.y;
            acc[cc][2] += p0 * m2.x + p1 * m2.y;
        }
    }

    int warp = threadIdx.x >> 5, lane = threadIdx.x & 31;
    #pragma unroll
    for (int cc = 0; cc < CG; cc++) {
        #pragma unroll
        for (int k = 0; k < 3; k++) {
            float s = acc[cc][k];
            #pragma unroll
            for (int off = 16; off; off >>= 1)
                s += __shfl_down_sync(0xFFFFFFFFu, s, off);
            if (lane == 0) red_s[warp][cc*3 + k] = s;
        }
    }
    __syncthreads();
    if (threadIdx.x < 24) {
        float s = 0.f;
        #pragma unroll
        for (int w8 = 0; w8 < 8; w8++) s += red_s[w8][threadIdx.x];
        int cc = threadIdx.x / 3, k = threadIdx.x % 3;
        int c = cg * CG + cc;
        g_feat[((size_t)(b*TT + t) * KK + k) * CC + c] = s * (1.0f / (float)HWPIX);
    }
}

// ---------------------------------------------------------------------------
// GCN kernel A: Wc[c][e] = sum_d W_emb[d][c] * W_gcn[d][e]
__global__ __launch_bounds__(192) void wc_kernel(const float* __restrict__ W_emb,
                                                 const float* __restrict__ W_gcn) {
    __shared__ float col[CC];
    int c = blockIdx.x, e = threadIdx.x;
    if (threadIdx.x < CC) col[threadIdx.x] = W_emb[(size_t)threadIdx.x * CC + c];
    __syncthreads();
    float acc = 0.f;
    #pragma unroll 8
    for (int d = 0; d < CC; d++)
        acc += col[d] * __ldg(&W_gcn[(size_t)d * CC + e]);
    g_Wc[c*CC + e] = acc;
}

// ---------------------------------------------------------------------------
// Fused GCN kernel: per-batch block does gram + softmax + sup + out, all smem.
// grid = BB (8 blocks) x 384 threads.
__global__ __launch_bounds__(384) void gcn_fused_kernel(const float* __restrict__ b_gcn) {
    __shared__ float node_s[NN*CC];     // 13.8 KB
    __shared__ float sup_s[NN*CC];      // 13.8 KB
    __shared__ float adj_s[NN*NN];      // 1.3 KB

    int b = blockIdx.x;
    int tid = threadIdx.x;              // 0..383

    const float* fb = g_feat + (size_t)b * NN * CC;
    for (int j = tid; j < NN*CC; j += 384)
        node_s[j] = fb[j];
    __syncthreads();

    // Gram: 324 dot products, one per thread
    if (tid < NN*NN) {
        int n = tid / NN, m = tid % NN;
        float s = 0.f;
        #pragma unroll 4
        for (int c = 0; c < CC; c++)
            s += node_s[n*CC + c] * node_s[m*CC + c];
        adj_s[tid] = s;
    }
    __syncthreads();

    // Row softmax: one thread per row
    if (tid < NN) {
        float mx = -1e30f;
        #pragma unroll
        for (int m = 0; m < NN; m++) mx = fmaxf(mx, adj_s[tid*NN + m]);
        float sm = 0.f;
        #pragma unroll
        for (int m = 0; m < NN; m++) { float e = expf(adj_s[tid*NN + m] - mx); adj_s[tid*NN + m] = e; sm += e; }
        float inv = 1.0f / sm;
        #pragma unroll
        for (int m = 0; m < NN; m++) adj_s[tid*NN + m] *= inv;
    }

    // sup[n][d] = sum_c node[n][c] * Wc[c][d]   (concurrent with softmax)
    {
        int d = tid % CC;           // 0..191
        int half = tid / CC;        // 0 or 1
        float acc[9];
        #pragma unroll
        for (int q = 0; q < 9; q++) acc[q] = 0.f;
        for (int c = 0; c < CC; c++) {
            float w = __ldg(&g_Wc[c*CC + d]);
            #pragma unroll
            for (int q = 0; q < 9; q++)
                acc[q] += node_s[(half*9 + q)*CC + c] * w;
        }
        #pragma unroll
        for (int q = 0; q < 9; q++) sup_s[(half*9 + q)*CC + d] = acc[q];
    }
    __syncthreads();

    // out[n][d] = b_gcn[d] + sum_m adj[n][m] * sup[m][d]
    {
        int d = tid % CC;
        int half = tid / CC;
        float bg = __ldg(&b_gcn[d]);
        #pragma unroll
        for (int q = 0; q < 9; q++) {
            int n = half*9 + q;
            float o = bg;
            #pragma unroll
            for (int m = 0; m < NN; m++) o += adj_s[n*NN + m] * sup_s[m*CC + d];
            g_outk[((size_t)b*NN + n)*CC + d] = o;
        }
    }
}

// ---------------------------------------------------------------------------
// Kernel 3: residual scatter + add (exact R2 structure — measured 156.4us,
// 71.1% DRAM; no cache hints).
__global__ __launch_bounds__(256) void scatter_kernel(const float* __restrict__ x,
                                                      const int* __restrict__ masks,
                                                      float* __restrict__ out) {
    int tb = blockIdx.x;
    int cg = blockIdx.y;
    int t = tb / BB, b = tb % BB;

    __shared__ float mf[3][PIX];
    __shared__ float rs[CG][3];

    const int* mp = masks + ((size_t)(b*TT + t) * KK) * PIX;
    for (int i = threadIdx.x; i < PIX; i += 256) {
        mf[0][i] = (float)(mp[i] & 1);
        mf[1][i] = (float)(mp[PIX + i] & 1);
        mf[2][i] = (float)(mp[2*PIX + i] & 1);
    }
    if (threadIdx.x < CG*3) {
        int cc = threadIdx.x / 3, k = threadIdx.x % 3;
        rs[cc][k] = g_outk[((size_t)(b*TT + t) * KK + k) * CC + cg*CG + cc];
    }
    __syncthreads();

    float r[CG][3];
    #pragma unroll
    for (int cc = 0; cc < CG; cc++) {
        r[cc][0] = rs[cc][0]; r[cc][1] = rs[cc][1]; r[cc][2] = rs[cc][2];
    }

    size_t plane0 = ((size_t)(t*BB + b)*CC + cg*CG) * HWPIX;
    const float* xbase = x + plane0;
    float*       obase = out + plane0;

    for (int i4 = threadIdx.x; i4 < HWPIX/4; i4 += 256) {
        int lin = i4 * 4;
        int h = lin / WW;
        int w = lin - h * WW;
        int mb = (h >> 1) * W0 + (w >> 1);
        float2 m0 = *(const float2*)&mf[0][mb];
        float2 m1 = *(const float2*)&mf[1][mb];
        float2 m2 = *(const float2*)&mf[2][mb];
        #pragma unroll
        for (int cc = 0; cc < CG; cc++) {
            float4 v = *(const float4*)(xbase + (size_t)cc*HWPIX + lin);
            float c0 = r[cc][0]*m0.x + r[cc][1]*m1.x + r[cc][2]*m2.x;
            float c1 = r[cc][0]*m0.y + r[cc][1]*m1.y + r[cc][2]*m2.y;
            float4 o;
            o.x = v.x + c0; o.y = v.y + c0;
            o.z = v.z + c1; o.w = v.w + c1;
            *(float4*)(obase + (size_t)cc*HWPIX + lin) = o;
        }
    }
}

// ---------------------------------------------------------------------------
extern "C" void kernel_launch(void* const* d_in, const int* in_sizes, int n_in,
                              void* d_out, int out_size) {
    const float* x      = (const float*)d_in[0];
    const int*   masks  = (const int*)  d_in[1];
    const float* W_emb  = (const float*)d_in[2];
    const float* W_gcn  = (const float*)d_in[3];
    const float* b_gcn  = (const float*)d_in[4];
    float* out = (float*)d_out;

    dim3 grid(TT*BB, CC/CG);

    wc_kernel<<<CC, 192>>>(W_emb, W_gcn);
    pool_kernel<<<grid, 256>>>(x, masks);
    gcn_fused_kernel<<<BB, 384>>>(b_gcn);
    scatter_kernel<<<grid, 256>>>(x, masks, out);
}

// round 6
// speedup vs baseline: 1.1147x; 1.1036x over previous
#include <cuda_runtime.h>
#include <cuda_bf16.h>
#include <stdint.h>

// Problem constants
#define TT 6
#define BB 8
#define CC 192
#define HH 112
#define WW 112
#define KK 3
#define H0 56
#define W0 56
#define HWPIX (HH*WW)          // 12544
#define PIX (H0*W0)            // 3136
#define NN (TT*KK)             // 18 nodes
#define CG 8                   // channels per block in streaming kernels
#define NPOOLB (TT*BB*(CC/CG)) // 1152 pool blocks

// Scratch (static device globals — no allocation)
__device__ float g_feat[BB*NN*CC];          // node features [B][N=T*K][C]
__device__ float g_Wc[CC*CC];               // W_emb^T @ W_gcn
__device__ float g_adj[BB*NN*NN];           // softmaxed adjacency
__device__ float g_sup[BB*NN*CC];           // node @ Wc

// ---------------------------------------------------------------------------
// Kernel 1: wc ∥ pool in one launch.
// blocks [0,192):    Wc[c][e] = sum_d W_emb[d][c] * W_gcn[d][e]
// blocks [192,1344): masked adaptive pooling (exact R2 structure, 82.6us).
__global__ __launch_bounds__(256) void poolwc_kernel(const float* __restrict__ x,
                                                     const int* __restrict__ masks,
                                                     const float* __restrict__ W_emb,
                                                     const float* __restrict__ W_gcn) {
    __shared__ float mf[3][PIX];      // pool masks; wc reuses mf[0][0..191]
    __shared__ float red_s[8][24];

    if (blockIdx.x < CC) {
        // ---- wc block ----
        int c = blockIdx.x;
        if (threadIdx.x < CC) mf[0][threadIdx.x] = W_emb[(size_t)threadIdx.x * CC + c];
        __syncthreads();
        if (threadIdx.x < CC) {
            int e = threadIdx.x;
            float acc = 0.f;
            #pragma unroll 8
            for (int d = 0; d < CC; d++)
                acc += mf[0][d] * __ldg(&W_gcn[(size_t)d * CC + e]);
            g_Wc[c*CC + e] = acc;
        }
        return;
    }

    // ---- pool block ----
    int pb = blockIdx.x - CC;
    int tb = pb % (TT*BB);        // t*B + b
    int cg = pb / (TT*BB);        // channel group
    int t = tb / BB, b = tb % BB;

    const int* mp = masks + ((size_t)(b*TT + t) * KK) * PIX;
    for (int i = threadIdx.x; i < PIX; i += 256) {
        mf[0][i] = (float)(mp[i] & 1);
        mf[1][i] = (float)(mp[PIX + i] & 1);
        mf[2][i] = (float)(mp[2*PIX + i] & 1);
    }
    __syncthreads();

    const float* xbase = x + ((size_t)(t*BB + b)*CC + cg*CG) * HWPIX;

    float acc[CG][3];
    #pragma unroll
    for (int cc = 0; cc < CG; cc++) {
        acc[cc][0] = 0.f; acc[cc][1] = 0.f; acc[cc][2] = 0.f;
    }

    for (int i4 = threadIdx.x; i4 < HWPIX/4; i4 += 256) {
        int lin = i4 * 4;
        int h = lin / WW;
        int w = lin - h * WW;
        int mb = (h >> 1) * W0 + (w >> 1);
        float2 m0 = *(const float2*)&mf[0][mb];
        float2 m1 = *(const float2*)&mf[1][mb];
        float2 m2 = *(const float2*)&mf[2][mb];
        #pragma unroll
        for (int cc = 0; cc < CG; cc++) {
            float4 v = *(const float4*)(xbase + (size_t)cc*HWPIX + lin);
            float p0 = v.x + v.y, p1 = v.z + v.w;
            acc[cc][0] += p0 * m0.x + p1 * m0.y;
            acc[cc][1] += p0 * m1.x + p1 * m1.y;
            acc[cc][2] += p0 * m2.x + p1 * m2.y;
        }
    }

    int warp = threadIdx.x >> 5, lane = threadIdx.x & 31;
    #pragma unroll
    for (int cc = 0; cc < CG; cc++) {
        #pragma unroll
        for (int k = 0; k < 3; k++) {
            float s = acc[cc][k];
            #pragma unroll
            for (int off = 16; off; off >>= 1)
                s += __shfl_down_sync(0xFFFFFFFFu, s, off);
            if (lane == 0) red_s[warp][cc*3 + k] = s;
        }
    }
    __syncthreads();
    if (threadIdx.x < 24) {
        float s = 0.f;
        #pragma unroll
        for (int w8 = 0; w8 < 8; w8++) s += red_s[w8][threadIdx.x];
        int cc = threadIdx.x / 3, k = threadIdx.x % 3;
        int c = cg * CG + cc;
        g_feat[((size_t)(b*TT + t) * KK + k) * CC + c] = s * (1.0f / (float)HWPIX);
    }
}

// ---------------------------------------------------------------------------
// GCN kernel S (exact R3 structure): per (n, b) block — gram row + softmax ->
// g_adj row, and sup row = node_n @ Wc -> g_sup. grid (NN, BB) x 192 threads.
__global__ __launch_bounds__(192) void gcn_s_kernel() {
    __shared__ float node_s[NN*CC];
    __shared__ float dots[NN];

    int n = blockIdx.x, b = blockIdx.y;
    int tid = threadIdx.x;
    int warp = tid >> 5, lane = tid & 31;

    const float* fb = g_feat + (size_t)b * NN * CC;
    for (int j = tid; j < NN*CC; j += 192)
        node_s[j] = fb[j];
    __syncthreads();

    // gram row: warp w handles m = w*3 + q (6 warps x 3 = 18)
    #pragma unroll
    for (int q = 0; q < 3; q++) {
        int m = warp * 3 + q;
        float s = 0.f;
        #pragma unroll
        for (int j = 0; j < 6; j++) {
            int c = lane + 32*j;
            s += node_s[n*CC + c] * node_s[m*CC + c];
        }
        #pragma unroll
        for (int off = 16; off; off >>= 1)
            s += __shfl_down_sync(0xFFFFFFFFu, s, off);
        if (lane == 0) dots[m] = s;
    }
    __syncthreads();

    if (tid == 0) {
        float mx = -1e30f;
        #pragma unroll
        for (int m = 0; m < NN; m++) mx = fmaxf(mx, dots[m]);
        float sm = 0.f;
        #pragma unroll
        for (int m = 0; m < NN; m++) { float e = expf(dots[m] - mx); dots[m] = e; sm += e; }
        float inv = 1.0f / sm;
        #pragma unroll
        for (int m = 0; m < NN; m++) dots[m] *= inv;
    }
    __syncthreads();
    if (tid < NN) g_adj[((size_t)b*NN + n)*NN + tid] = dots[tid];

    // sup row: sup[e] = sum_c node_n[c] * Wc[c][e]  (Wc coalesced)
    float acc = 0.f;
    const float* nrow = node_s + n*CC;
    #pragma unroll 4
    for (int c = 0; c < CC; c++)
        acc += nrow[c] * g_Wc[c*CC + tid];
    g_sup[((size_t)b*NN + n)*CC + tid] = acc;
}

// ---------------------------------------------------------------------------
// Kernel 3: gcn_o ∥ residual scatter.
// Warp 0 computes the block's 24 outk values (hidden under warps 1-7's mask
// smem fill); streaming part is the exact R2 structure (156.4us / 75% DRAM).
__global__ __launch_bounds__(256) void scatter_kernel(const float* __restrict__ x,
                                                      const int* __restrict__ masks,
                                                      const float* __restrict__ b_gcn,
                                                      float* __restrict__ out) {
    int tb = blockIdx.x;
    int cg = blockIdx.y;
    int t = tb / BB, b = tb % BB;

    __shared__ float mf[3][PIX];
    __shared__ float rs[CG][3];

    const int* mp = masks + ((size_t)(b*TT + t) * KK) * PIX;
    if (threadIdx.x >= 32) {
        for (int i = threadIdx.x - 32; i < PIX; i += 224) {
            mf[0][i] = (float)(mp[i] & 1);
            mf[1][i] = (float)(mp[PIX + i] & 1);
            mf[2][i] = (float)(mp[2*PIX + i] & 1);
        }
    } else if (threadIdx.x < 24) {
        // out[b][n][c] = b_gcn[c] + sum_m adj[b][n][m] * sup[b][m][c]
        int cc = threadIdx.x / 3, k = threadIdx.x % 3;
        int c = cg * CG + cc;
        int n = t * KK + k;
        const float* arow = g_adj + ((size_t)b*NN + n)*NN;
        const float* supb = g_sup + (size_t)b*NN*CC + c;
        float acc = __ldg(&b_gcn[c]);
        #pragma unroll
        for (int m = 0; m < NN; m++)
            acc += arow[m] * supb[(size_t)m*CC];
        rs[cc][k] = acc;
    }
    __syncthreads();

    float r[CG][3];
    #pragma unroll
    for (int cc = 0; cc < CG; cc++) {
        r[cc][0] = rs[cc][0]; r[cc][1] = rs[cc][1]; r[cc][2] = rs[cc][2];
    }

    size_t plane0 = ((size_t)(t*BB + b)*CC + cg*CG) * HWPIX;
    const float* xbase = x + plane0;
    float*       obase = out + plane0;

    for (int i4 = threadIdx.x; i4 < HWPIX/4; i4 += 256) {
        int lin = i4 * 4;
        int h = lin / WW;
        int w = lin - h * WW;
        int mb = (h >> 1) * W0 + (w >> 1);
        float2 m0 = *(const float2*)&mf[0][mb];
        float2 m1 = *(const float2*)&mf[1][mb];
        float2 m2 = *(const float2*)&mf[2][mb];
        #pragma unroll
        for (int cc = 0; cc < CG; cc++) {
            float4 v = *(const float4*)(xbase + (size_t)cc*HWPIX + lin);
            float c0 = r[cc][0]*m0.x + r[cc][1]*m1.x + r[cc][2]*m2.x;
            float c1 = r[cc][0]*m0.y + r[cc][1]*m1.y + r[cc][2]*m2.y;
            float4 o;
            o.x = v.x + c0; o.y = v.y + c0;
            o.z = v.z + c1; o.w = v.w + c1;
            *(float4*)(obase + (size_t)cc*HWPIX + lin) = o;
        }
    }
}

// ---------------------------------------------------------------------------
extern "C" void kernel_launch(void* const* d_in, const int* in_sizes, int n_in,
                              void* d_out, int out_size) {
    const float* x      = (const float*)d_in[0];
    const int*   masks  = (const int*)  d_in[1];
    const float* W_emb  = (const float*)d_in[2];
    const float* W_gcn  = (const float*)d_in[3];
    const float* b_gcn  = (const float*)d_in[4];
    float* out = (float*)d_out;

    poolwc_kernel<<<CC + NPOOLB, 256>>>(x, masks, W_emb, W_gcn);
    gcn_s_kernel<<<dim3(NN, BB), 192>>>();
    scatter_kernel<<<dim3(TT*BB, CC/CG), 256>>>(x, masks, b_gcn, out);
}